// round 15
// baseline (speedup 1.0000x reference)
#include <cuda_runtime.h>
#include <cuda_fp16.h>
#include <math.h>
#include <stdint.h>

#define NN 100000
#define NE 500000
#define DIMC 256
#define NH 8
#define NBLK 391   // ceil(NN/256)

// Dynamic smem layout (bytes):
//   A stage s (s=0,1): base + s*10240          (128 rows x 32 fp16, pad 40)
//   B stage s:         base + 20480 + s*5120   (64 rows x 32 fp16, pad 40)
#define A_STAGE_BYTES 10240
#define B_BASE        20480
#define B_STAGE_BYTES 5120
#define DYN_SMEM      30720

// ---------------------------------------------------------------------------
// Device-global scratch (no allocation allowed in kernel_launch)
// ---------------------------------------------------------------------------
__device__ __half g_Qh[NN * DIMC];
__device__ __half g_Kh[NN * DIMC];
__device__ __half g_Vh[NN * DIMC];
__device__ float g_S[NE * NH];
__device__ float g_cs[DIMC];
__device__ float g_cs2[DIMC];
__device__ int g_src[NE];
__device__ int g_dst[NE];
__device__ int g_cnt[NN];
__device__ int g_off[NN + 1];
__device__ int g_cur[NN];
__device__ int g_blkSum[512];
__device__ int g_psrc[NE];
__device__ int g_peid[NE];
__device__ __half g_W[768 * DIMC];    // [n][k], QKV concat, fp16 RN
__device__ __half g_WE[DIMC * DIMC];  // [n][k], fp16 RN

// ---------------------------------------------------------------------------
// Warp-MMA helpers (portable PTX: ldmatrix + mma.sync + cp.async, sm_80+)
// ---------------------------------------------------------------------------
__device__ __forceinline__ void ldsm_x4(uint32_t* r, uint32_t addr) {
    asm volatile("ldmatrix.sync.aligned.m8n8.x4.shared.b16 {%0,%1,%2,%3}, [%4];"
                 : "=r"(r[0]), "=r"(r[1]), "=r"(r[2]), "=r"(r[3]) : "r"(addr));
}
__device__ __forceinline__ void mma_f16(float* d, const uint32_t* a, const uint32_t* b) {
    asm volatile(
        "mma.sync.aligned.m16n8k16.row.col.f32.f16.f16.f32 "
        "{%0,%1,%2,%3}, {%4,%5,%6,%7}, {%8,%9}, {%0,%1,%2,%3};"
        : "+f"(d[0]), "+f"(d[1]), "+f"(d[2]), "+f"(d[3])
        : "r"(a[0]), "r"(a[1]), "r"(a[2]), "r"(a[3]), "r"(b[0]), "r"(b[1]));
}
__device__ __forceinline__ uint32_t smem_u32(const void* p) {
    uint32_t a;
    asm("{ .reg .u64 t; cvta.to.shared.u64 t, %1; cvt.u32.u64 %0, t; }"
        : "=r"(a) : "l"(p));
    return a;
}
__device__ __forceinline__ void cp_async16(uint32_t saddr, const void* gptr) {
    asm volatile("cp.async.cg.shared.global [%0], [%1], 16;"
                 :: "r"(saddr), "l"(gptr) : "memory");
}
__device__ __forceinline__ void cp_commit() {
    asm volatile("cp.async.commit_group;" ::: "memory");
}
__device__ __forceinline__ void cp_wait0() {
    asm volatile("cp.async.wait_group 0;" ::: "memory");
}

// ---------------------------------------------------------------------------
// Zero small accumulators (BN sums + histogram).
// ---------------------------------------------------------------------------
__global__ void zero_kernel() {
    int i = blockIdx.x * 256 + threadIdx.x;
    if (i < NN) g_cnt[i] = 0;
    if (i < DIMC) { g_cs[i] = 0.0f; g_cs2[i] = 0.0f; }
}

// ---------------------------------------------------------------------------
// edge_index -> int32 src/dst + dst histogram (int64 or int32 payload).
// ---------------------------------------------------------------------------
__global__ void cvt_idx_kernel(const long long* __restrict__ e64) {
    const int* e32 = (const int*)e64;
    bool is64 = true;
    #pragma unroll
    for (int i = 0; i < 64; ++i)
        if ((e64[i] >> 32) != 0) is64 = false;
    long stride = (long)gridDim.x * blockDim.x;
    for (long e = (long)blockIdx.x * blockDim.x + threadIdx.x; e < NE; e += stride) {
        int s, d;
        if (is64) { s = (int)e64[e]; d = (int)e64[NE + e]; }
        else      { s = e32[e];      d = e32[NE + e];      }
        g_src[e] = s;
        g_dst[e] = d;
        atomicAdd(&g_cnt[d], 1);
    }
}

// ---------------------------------------------------------------------------
// 3-kernel exclusive scan of g_cnt -> g_off / g_cur.
// ---------------------------------------------------------------------------
__global__ void scan1_kernel() {
    __shared__ int sh[256];
    int i = blockIdx.x * 256 + threadIdx.x;
    int v = (i < NN) ? g_cnt[i] : 0;
    sh[threadIdx.x] = v;
    __syncthreads();
    for (int d = 1; d < 256; d <<= 1) {
        int t = (threadIdx.x >= d) ? sh[threadIdx.x - d] : 0;
        __syncthreads();
        sh[threadIdx.x] += t;
        __syncthreads();
    }
    if (i < NN) g_off[i] = sh[threadIdx.x] - v;
    if (threadIdx.x == 255) g_blkSum[blockIdx.x] = sh[255];
}
__global__ void scan2_kernel() {
    __shared__ int sh[512];
    int v = (threadIdx.x < NBLK) ? g_blkSum[threadIdx.x] : 0;
    sh[threadIdx.x] = v;
    __syncthreads();
    for (int d = 1; d < 512; d <<= 1) {
        int t = (threadIdx.x >= d) ? sh[threadIdx.x - d] : 0;
        __syncthreads();
        sh[threadIdx.x] += t;
        __syncthreads();
    }
    if (threadIdx.x < NBLK) g_blkSum[threadIdx.x] = sh[threadIdx.x] - v;
}
__global__ void scan3_kernel() {
    int i = blockIdx.x * 256 + threadIdx.x;
    if (i < NN) {
        int o = g_off[i] + g_blkSum[blockIdx.x];
        g_off[i] = o;
        g_cur[i] = o;
    }
    if (i == 0) g_off[NN] = NE;
}

// ---------------------------------------------------------------------------
// Build dst-sorted edge list (CSR payload).
// ---------------------------------------------------------------------------
__global__ void build_kernel() {
    int e = blockIdx.x * 256 + threadIdx.x;
    if (e < NE) {
        int d = g_dst[e];
        int pos = atomicAdd(&g_cur[d], 1);
        g_psrc[pos] = g_src[e];
        g_peid[pos] = e;
    }
}

// ---------------------------------------------------------------------------
// Weights transposed into B-operand layout [n][k], fp16 round-to-nearest.
// ---------------------------------------------------------------------------
__global__ void prep_w_kernel(const float* __restrict__ WQ, const float* __restrict__ WK,
                              const float* __restrict__ WV, const float* __restrict__ WE) {
    int i = blockIdx.x * 256 + threadIdx.x;
    if (i < 768 * DIMC) {
        int n = i >> 8;
        int k = i & 255;
        int m = n >> 8, nn = n & 255;
        const float* W = (m == 0) ? WQ : (m == 1) ? WK : WV;
        g_W[i] = __float2half_rn(W[k * DIMC + nn]);
    } else {
        int j = i - 768 * DIMC;
        int n = j >> 8, k = j & 255;
        g_WE[j] = __float2half_rn(WE[k * DIMC + n]);
    }
}

// ---------------------------------------------------------------------------
// Convert & store one A chunk (4 float4 per thread) to fp16 smem stage.
// ---------------------------------------------------------------------------
__device__ __forceinline__ void stsA(char* stage, const float4* v4,
                                     const int* aRow, int aC4) {
    __half* sA = (__half*)stage;
    #pragma unroll
    for (int l = 0; l < 4; ++l) {
        float4 v = v4[l];
        __half2 h01 = __floats2half2_rn(v.x, v.y);
        __half2 h23 = __floats2half2_rn(v.z, v.w);
        int row = aRow[l];
        *(uint2*)(sA + row * 40 + aC4 * 4) =
            make_uint2(*(uint32_t*)&h01, *(uint32_t*)&h23);
    }
}

// ---------------------------------------------------------------------------
// Warp-MMA fp16 GEMM, 128x64 block tile (8 warps of 32x32), 3 CTAs/SM.
// K=256 in 8 chunks of 32; double-buffered (STS A; wait B; bar; issue B+1; MMA).
// EDGE=0: writes Q/K/V fp16, grid (12, 782):  bx -> matrix (bx>>2), colb (bx&3)*64.
// EDGE=1: per-edge head scores -> g_S, grid (4, 3907): warp wn covers ONE head.
// ---------------------------------------------------------------------------
template<int EDGE>
__global__ void __launch_bounds__(256, 3) mma_gemm_kernel(const float* __restrict__ Asrc) {
    extern __shared__ __align__(16) char dsm[];
    __shared__ int Ssrc[128], Sdst[128];

    const int tid  = threadIdx.x;
    const int wid  = tid >> 5;
    const int lane = tid & 31;
    const int wm   = wid & 3;    // 4 M-groups of 32 rows
    const int wn   = wid >> 2;   // 2 N-groups of 32 cols
    const int quad = lane & 3;
    const int qrow = lane >> 2;

    const int row0  = blockIdx.y * 128;
    const int nbase = blockIdx.x * 64;
    const int Mtot  = EDGE ? NE : NN;

    if (EDGE && tid < 128) {
        int ge = row0 + tid;
        if (ge > NE - 1) ge = NE - 1;
        Ssrc[tid] = g_src[ge];
        Sdst[tid] = g_dst[ge];
    }

    const float4* A4 = (const float4*)Asrc;
    const uint4* B4 = EDGE ? (const uint4*)g_WE : (const uint4*)g_W;

    float acc[2][4][4] = {};

    const uint32_t base = smem_u32(dsm);
    const uint32_t aOff = (uint32_t)((wm * 32 + (lane & 15)) * 80 + (lane >> 4) * 16);
    // x4 B layout: lanes 0-7 rows n..n+7 (k-half 0), 8-15 same rows (k-half 1),
    // 16-23 rows n+8..n+15 (k-half 0), 24-31 (k-half 1).
    const uint32_t bOffX4 = (uint32_t)((wn * 32 + (lane & 7) + (lane >> 4) * 8) * 80 +
                                       ((lane >> 3) & 1) * 16);

    const int aRow[4] = { (tid + 0) >> 3, (tid + 256) >> 3, (tid + 512) >> 3, (tid + 768) >> 3 };
    const int aC4 = tid & 7;
    long aRowG[4];
    #pragma unroll
    for (int l = 0; l < 4; ++l) aRowG[l] = min(row0 + aRow[l], Mtot - 1);
    // B chunk: 64 rows x 32 fp16 = 256 x 16B; 1 per thread.
    const int bRow = tid >> 2;
    const int bC4  = tid & 3;

    float4 aPre[4];
    #pragma unroll
    for (int l = 0; l < 4; ++l) aPre[l] = A4[aRowG[l] * 64 + 0 + aC4];
    {
        const uint4* gsrc = B4 + (long)(nbase + bRow) * 32 + 0 + bC4;
        cp_async16(base + B_BASE + (uint32_t)(bRow * 80 + bC4 * 16), gsrc);
        cp_commit();
    }

    for (int kc = 0; kc < 8; ++kc) {
        const int st = kc & 1;
        const uint32_t aBase = base + st * A_STAGE_BYTES;
        const uint32_t bBase = base + B_BASE + st * B_STAGE_BYTES;

        stsA(dsm + st * A_STAGE_BYTES, aPre, aRow, aC4);

        cp_wait0();
        __syncthreads();

        if (kc < 7) {
            const uint4* gsrc = B4 + (long)(nbase + bRow) * 32 + (kc + 1) * 4 + bC4;
            cp_async16(base + B_BASE + (st ^ 1) * B_STAGE_BYTES +
                       (uint32_t)(bRow * 80 + bC4 * 16), gsrc);
            cp_commit();
            #pragma unroll
            for (int l = 0; l < 4; ++l)
                aPre[l] = A4[aRowG[l] * 64 + (kc + 1) * 8 + aC4];
        }

        #pragma unroll
        for (int s = 0; s < 2; ++s) {
            uint32_t ah[2][4];
            #pragma unroll
            for (int mi = 0; mi < 2; ++mi) {
                uint32_t o = aOff + (uint32_t)(mi * 16 * 80 + s * 32);
                ldsm_x4(ah[mi], aBase + o);
            }
            #pragma unroll
            for (int nj = 0; nj < 2; ++nj) {
                const int ni = nj * 2;
                uint32_t bo = bOffX4 + (uint32_t)(nj * 16 * 80 + s * 32);
                uint32_t bf[4];                  // [0:2)=ni, [2:4)=ni+1
                ldsm_x4(bf, bBase + bo);
                mma_f16(acc[0][ni],     ah[0], bf + 0);
                mma_f16(acc[0][ni + 1], ah[0], bf + 2);
                mma_f16(acc[1][ni],     ah[1], bf + 0);
                mma_f16(acc[1][ni + 1], ah[1], bf + 2);
            }
        }
    }

    if (EDGE) {
        // Warp wn covers exactly one head: cols nbase + wn*32 .. +31.
        const float scale = 0.17677669529663687f;  // 1/sqrt(32)
        const int hIdx = (nbase >> 5) + wn;
        #pragma unroll
        for (int mi = 0; mi < 2; ++mi) {
            #pragma unroll
            for (int rh = 0; rh < 2; ++rh) {
                int r  = wm * 32 + mi * 16 + qrow + rh * 8;
                int ge = row0 + r;
                const __half* Kr = g_Kh + (long)Ssrc[r] * DIMC + nbase + wn * 32;
                const __half* Qr = g_Qh + (long)Sdst[r] * DIMC + nbase + wn * 32;
                float p = 0.0f;
                #pragma unroll
                for (int ni = 0; ni < 4; ++ni) {
                    int c = ni * 8 + quad * 2;
                    float2 kv = __half22float2(*(const __half2*)(Kr + c));
                    float2 qv = __half22float2(*(const __half2*)(Qr + c));
                    p += acc[mi][ni][rh * 2 + 0] * kv.x * qv.x;
                    p += acc[mi][ni][rh * 2 + 1] * kv.y * qv.y;
                }
                p += __shfl_xor_sync(0xffffffffu, p, 1);
                p += __shfl_xor_sync(0xffffffffu, p, 2);
                if (quad == 0 && ge < NE) {
                    float sv = fminf(5.0f, fmaxf(-5.0f, p * scale));
                    g_S[(long)ge * NH + hIdx] = expf(sv);
                }
            }
        }
    } else {
        int bx = blockIdx.x;
        __half* Cout = (bx < 4) ? g_Qh : (bx < 8) ? g_Kh : g_Vh;
        int colb = (bx & 3) * 64;
        #pragma unroll
        for (int mi = 0; mi < 2; ++mi) {
            #pragma unroll
            for (int ni = 0; ni < 4; ++ni) {
                int r = row0 + wm * 32 + mi * 16 + qrow;
                int c = colb + wn * 32 + ni * 8 + quad * 2;
                if (r < NN) {
                    __half2 v = __floats2half2_rn(acc[mi][ni][0], acc[mi][ni][1]);
                    *(__half2*)(Cout + (long)r * DIMC + c) = v;
                }
                if (r + 8 < NN) {
                    __half2 v = __floats2half2_rn(acc[mi][ni][2], acc[mi][ni][3]);
                    *(__half2*)(Cout + (long)(r + 8) * DIMC + c) = v;
                }
            }
        }
    }
}

// ---------------------------------------------------------------------------
// Gather + residual: one CTA per node; thread = column. No atomics.
// ---------------------------------------------------------------------------
__global__ void gather_resid_kernel(const float* __restrict__ x,
                                    float* __restrict__ out) {
    int n   = blockIdx.x;
    int tid = threadIdx.x;
    int h   = tid >> 5;
    int beg = g_off[n];
    int end = g_off[n + 1];

    float acc = 0.0f, zacc = 0.0f;
    int e = beg;
    for (; e + 1 < end; e += 2) {
        int s0 = g_psrc[e],     s1 = g_psrc[e + 1];
        int i0 = g_peid[e],     i1 = g_peid[e + 1];
        float w0 = g_S[(long)i0 * NH + h];
        float w1 = g_S[(long)i1 * NH + h];
        float v0 = __half2float(g_Vh[(long)s0 * DIMC + tid]);
        float v1 = __half2float(g_Vh[(long)s1 * DIMC + tid]);
        acc += v0 * w0;
        acc += v1 * w1;
        zacc += w0 + w1;
    }
    if (e < end) {
        int s0 = g_psrc[e];
        int i0 = g_peid[e];
        float w0 = g_S[(long)i0 * NH + h];
        acc += __half2float(g_Vh[(long)s0 * DIMC + tid]) * w0;
        zacc += w0;
    }
    out[(long)n * DIMC + tid] = x[(long)n * DIMC + tid] + acc / (zacc + 1e-6f);
}

// ---------------------------------------------------------------------------
// BN column sums over out, then normalize.
// ---------------------------------------------------------------------------
__global__ void stats_kernel(const float* __restrict__ out) {
    int c = threadIdx.x;
    int r0 = blockIdx.x * 256;
    int rend = min(NN, r0 + 256);
    float s = 0.0f, s2 = 0.0f;
    for (int n = r0; n < rend; ++n) {
        float hv = out[(long)n * DIMC + c];
        s += hv;
        s2 += hv * hv;
    }
    atomicAdd(&g_cs[c], s);
    atomicAdd(&g_cs2[c], s2);
}

__global__ void bn_norm_kernel(float* __restrict__ out,
                               const float* __restrict__ gamma,
                               const float* __restrict__ beta) {
    long total = (long)NN * DIMC;
    long stride = (long)gridDim.x * blockDim.x;
    const float invN = 1.0f / (float)NN;
    for (long i = (long)blockIdx.x * blockDim.x + threadIdx.x; i < total; i += stride) {
        int c = (int)(i & (DIMC - 1));
        float mean = g_cs[c] * invN;
        float var = g_cs2[c] * invN - mean * mean;
        out[i] = (out[i] - mean) * rsqrtf(var + 1e-5f) * gamma[c] + beta[c];
    }
}

extern "C" void kernel_launch(void* const* d_in, const int* in_sizes, int n_in,
                              void* d_out, int out_size) {
    const float* x     = (const float*)d_in[0];
    const float* ea    = (const float*)d_in[1];
    const float* WQ    = (const float*)d_in[2];
    const float* WK    = (const float*)d_in[3];
    const float* WE    = (const float*)d_in[4];
    const float* WV    = (const float*)d_in[5];
    const float* gamma = (const float*)d_in[6];
    const float* beta  = (const float*)d_in[7];
    const long long* eidx = (const long long*)d_in[8];
    float* out = (float*)d_out;

    zero_kernel<<<NBLK, 256>>>();
    cvt_idx_kernel<<<512, 256>>>(eidx);
    scan1_kernel<<<NBLK, 256>>>();
    scan2_kernel<<<1, 512>>>();
    scan3_kernel<<<NBLK, 256>>>();
    build_kernel<<<(NE + 255) / 256, 256>>>();
    prep_w_kernel<<<1024, 256>>>(WQ, WK, WV, WE);

    // QKV: x = N-tile (12: matrix*4 + 64-col tile), y = row-tile (782).
    mma_gemm_kernel<0><<<dim3(12, 782), 256, DYN_SMEM>>>(x);
    // Edge: x = N-tile (4 x 64 cols = 2 heads each), y = row-tile (3907).
    mma_gemm_kernel<1><<<dim3(4, 3907), 256, DYN_SMEM>>>(ea);

    gather_resid_kernel<<<NN, 256>>>(x, out);
    stats_kernel<<<NBLK, 256>>>(out);
    bn_norm_kernel<<<2048, 256>>>(out, gamma, beta);
}

// round 16
// speedup vs baseline: 1.0879x; 1.0879x over previous
#include <cuda_runtime.h>
#include <cuda_fp16.h>
#include <math.h>
#include <stdint.h>

#define NN 100000
#define NE 500000
#define DIMC 256
#define NH 8
#define NBLK 391   // ceil(NN/256)

// Dynamic smem layout (bytes):
//   A stage s (s=0,1): base + s*10240          (single fp16 copy of A chunk)
//   B stage s:         base + 20480 + s*10240  (single fp16 copy of W chunk)
#define A_STAGE_BYTES 10240
#define B_BASE        20480
#define B_STAGE_BYTES 10240
#define DYN_SMEM      40960

// ---------------------------------------------------------------------------
// Device-global scratch (no allocation allowed in kernel_launch)
// ---------------------------------------------------------------------------
__device__ __half g_Qh[NN * DIMC];
__device__ __half g_Kh[NN * DIMC];
__device__ __half g_Vh[NN * DIMC];
__device__ float g_S[NE * NH];
__device__ float g_cs[DIMC];
__device__ float g_cs2[DIMC];
__device__ int g_src[NE];
__device__ int g_dst[NE];
__device__ int g_cnt[NN];
__device__ int g_off[NN + 1];
__device__ int g_cur[NN];
__device__ int g_blkSum[512];
__device__ int g_psrc[NE];
__device__ int g_peid[NE];
__device__ __half g_W[768 * DIMC];    // [n][k], QKV concat, fp16 RN
__device__ __half g_WE[DIMC * DIMC];  // [n][k], fp16 RN

// ---------------------------------------------------------------------------
// Warp-MMA helpers (portable PTX: ldmatrix + mma.sync + cp.async, sm_80+)
// ---------------------------------------------------------------------------
__device__ __forceinline__ uint32_t smem_u32(const void* p) {
    uint32_t a;
    asm("{ .reg .u64 t; cvta.to.shared.u64 t, %1; cvt.u32.u64 %0, t; }"
        : "=r"(a) : "l"(p));
    return a;
}
__device__ __forceinline__ void ldsm_x4(uint32_t* r, uint32_t addr) {
    asm volatile("ldmatrix.sync.aligned.m8n8.x4.shared.b16 {%0,%1,%2,%3}, [%4];"
                 : "=r"(r[0]), "=r"(r[1]), "=r"(r[2]), "=r"(r[3]) : "r"(addr));
}
__device__ __forceinline__ void mma_f16(float* d, const uint32_t* a, const uint32_t* b) {
    asm volatile(
        "mma.sync.aligned.m16n8k16.row.col.f32.f16.f16.f32 "
        "{%0,%1,%2,%3}, {%4,%5,%6,%7}, {%8,%9}, {%0,%1,%2,%3};"
        : "+f"(d[0]), "+f"(d[1]), "+f"(d[2]), "+f"(d[3])
        : "r"(a[0]), "r"(a[1]), "r"(a[2]), "r"(a[3]), "r"(b[0]), "r"(b[1]));
}
__device__ __forceinline__ void cp_async16(uint32_t saddr, const void* gptr) {
    asm volatile("cp.async.cg.shared.global [%0], [%1], 16;"
                 :: "r"(saddr), "l"(gptr) : "memory");
}
__device__ __forceinline__ void cp_commit() {
    asm volatile("cp.async.commit_group;" ::: "memory");
}
__device__ __forceinline__ void cp_wait0() {
    asm volatile("cp.async.wait_group 0;" ::: "memory");
}

// ---------------------------------------------------------------------------
// Zero small accumulators (BN sums + histogram).
// ---------------------------------------------------------------------------
__global__ void zero_kernel() {
    int i = blockIdx.x * 256 + threadIdx.x;
    if (i < NN) g_cnt[i] = 0;
    if (i < DIMC) { g_cs[i] = 0.0f; g_cs2[i] = 0.0f; }
}

// ---------------------------------------------------------------------------
// edge_index -> int32 src/dst + dst histogram (int64 or int32 payload).
// ---------------------------------------------------------------------------
__global__ void cvt_idx_kernel(const long long* __restrict__ e64) {
    const int* e32 = (const int*)e64;
    bool is64 = true;
    #pragma unroll
    for (int i = 0; i < 64; ++i)
        if ((e64[i] >> 32) != 0) is64 = false;
    long stride = (long)gridDim.x * blockDim.x;
    for (long e = (long)blockIdx.x * blockDim.x + threadIdx.x; e < NE; e += stride) {
        int s, d;
        if (is64) { s = (int)e64[e]; d = (int)e64[NE + e]; }
        else      { s = e32[e];      d = e32[NE + e];      }
        g_src[e] = s;
        g_dst[e] = d;
        atomicAdd(&g_cnt[d], 1);
    }
}

// ---------------------------------------------------------------------------
// 3-kernel exclusive scan of g_cnt -> g_off / g_cur.
// ---------------------------------------------------------------------------
__global__ void scan1_kernel() {
    __shared__ int sh[256];
    int i = blockIdx.x * 256 + threadIdx.x;
    int v = (i < NN) ? g_cnt[i] : 0;
    sh[threadIdx.x] = v;
    __syncthreads();
    for (int d = 1; d < 256; d <<= 1) {
        int t = (threadIdx.x >= d) ? sh[threadIdx.x - d] : 0;
        __syncthreads();
        sh[threadIdx.x] += t;
        __syncthreads();
    }
    if (i < NN) g_off[i] = sh[threadIdx.x] - v;
    if (threadIdx.x == 255) g_blkSum[blockIdx.x] = sh[255];
}
__global__ void scan2_kernel() {
    __shared__ int sh[512];
    int v = (threadIdx.x < NBLK) ? g_blkSum[threadIdx.x] : 0;
    sh[threadIdx.x] = v;
    __syncthreads();
    for (int d = 1; d < 512; d <<= 1) {
        int t = (threadIdx.x >= d) ? sh[threadIdx.x - d] : 0;
        __syncthreads();
        sh[threadIdx.x] += t;
        __syncthreads();
    }
    if (threadIdx.x < NBLK) g_blkSum[threadIdx.x] = sh[threadIdx.x] - v;
}
__global__ void scan3_kernel() {
    int i = blockIdx.x * 256 + threadIdx.x;
    if (i < NN) {
        int o = g_off[i] + g_blkSum[blockIdx.x];
        g_off[i] = o;
        g_cur[i] = o;
    }
    if (i == 0) g_off[NN] = NE;
}

// ---------------------------------------------------------------------------
// Build dst-sorted edge list (CSR payload).
// ---------------------------------------------------------------------------
__global__ void build_kernel() {
    int e = blockIdx.x * 256 + threadIdx.x;
    if (e < NE) {
        int d = g_dst[e];
        int pos = atomicAdd(&g_cur[d], 1);
        g_psrc[pos] = g_src[e];
        g_peid[pos] = e;
    }
}

// ---------------------------------------------------------------------------
// Weights transposed into B-operand layout [n][k], fp16 round-to-nearest.
// ---------------------------------------------------------------------------
__global__ void prep_w_kernel(const float* __restrict__ WQ, const float* __restrict__ WK,
                              const float* __restrict__ WV, const float* __restrict__ WE) {
    int i = blockIdx.x * 256 + threadIdx.x;
    if (i < 768 * DIMC) {
        int n = i >> 8;
        int k = i & 255;
        int m = n >> 8, nn = n & 255;
        const float* W = (m == 0) ? WQ : (m == 1) ? WK : WV;
        g_W[i] = __float2half_rn(W[k * DIMC + nn]);
    } else {
        int j = i - 768 * DIMC;
        int n = j >> 8, k = j & 255;
        g_WE[j] = __float2half_rn(WE[k * DIMC + n]);
    }
}

// ---------------------------------------------------------------------------
// Convert & store one A chunk (4 float4 per thread) to fp16 smem stage.
// ---------------------------------------------------------------------------
__device__ __forceinline__ void stsA(char* stage, const float4* v4,
                                     const int* aRow, int aC4) {
    __half* sA = (__half*)stage;
    #pragma unroll
    for (int l = 0; l < 4; ++l) {
        float4 v = v4[l];
        __half2 h01 = __floats2half2_rn(v.x, v.y);
        __half2 h23 = __floats2half2_rn(v.z, v.w);
        int row = aRow[l];
        *(uint2*)(sA + row * 40 + aC4 * 4) =
            make_uint2(*(uint32_t*)&h01, *(uint32_t*)&h23);
    }
}

// ---------------------------------------------------------------------------
// Warp-MMA fp16 GEMM (1-pass), 128x128 block tile, K=256 in 8 chunks of 32.
// (round-14 best, byte-identical)
// EDGE=0: writes Q/K/V as fp16.  EDGE=1: per-edge head-score epilogue -> g_S.
// ---------------------------------------------------------------------------
template<int EDGE>
__global__ void __launch_bounds__(256, 2) mma_gemm_kernel(const float* __restrict__ Asrc) {
    extern __shared__ __align__(16) char dsm[];
    __shared__ int Ssrc[128], Sdst[128];

    const int tid  = threadIdx.x;
    const int wid  = tid >> 5;
    const int lane = tid & 31;
    const int wm   = wid & 3;
    const int wn   = wid >> 2;
    const int quad = lane & 3;
    const int qrow = lane >> 2;

    const int row0  = blockIdx.y * 128;
    const int nbase = blockIdx.x * 128;
    const int Mtot  = EDGE ? NE : NN;

    if (EDGE && tid < 128) {
        int ge = row0 + tid;
        if (ge > NE - 1) ge = NE - 1;
        Ssrc[tid] = g_src[ge];
        Sdst[tid] = g_dst[ge];
    }

    const float4* A4 = (const float4*)Asrc;
    const uint4* B4 = EDGE ? (const uint4*)g_WE : (const uint4*)g_W;

    float acc[2][8][4] = {};

    const uint32_t base = smem_u32(dsm);
    const uint32_t aOff = (uint32_t)((wm * 32 + (lane & 15)) * 80 + (lane >> 4) * 16);
    const uint32_t bOffX4 = (uint32_t)((wn * 64 + (lane & 7) + (lane >> 4) * 8) * 80 +
                                       ((lane >> 3) & 1) * 16);

    const int aRow[4] = { (tid + 0) >> 3, (tid + 256) >> 3, (tid + 512) >> 3, (tid + 768) >> 3 };
    const int aC4 = tid & 7;
    long aRowG[4];
    #pragma unroll
    for (int l = 0; l < 4; ++l) aRowG[l] = min(row0 + aRow[l], Mtot - 1);
    const int bRow[2] = { (tid + 0) >> 2, (tid + 256) >> 2 };
    const int bC4 = tid & 3;

    float4 aPre[4];
    #pragma unroll
    for (int l = 0; l < 4; ++l) aPre[l] = A4[aRowG[l] * 64 + 0 + aC4];
    {
        uint32_t bB = base + B_BASE;
        #pragma unroll
        for (int l = 0; l < 2; ++l) {
            const uint4* gsrc = B4 + (long)(nbase + bRow[l]) * 32 + 0 + bC4;
            cp_async16(bB + (uint32_t)(bRow[l] * 80 + bC4 * 16), gsrc);
        }
        cp_commit();
    }

    for (int kc = 0; kc < 8; ++kc) {
        const int st = kc & 1;
        const uint32_t aBase = base + st * A_STAGE_BYTES;
        const uint32_t bBase = base + B_BASE + st * B_STAGE_BYTES;

        stsA(dsm + st * A_STAGE_BYTES, aPre, aRow, aC4);

        cp_wait0();
        __syncthreads();

        if (kc < 7) {
            uint32_t bBn = base + B_BASE + (st ^ 1) * B_STAGE_BYTES;
            #pragma unroll
            for (int l = 0; l < 2; ++l) {
                const uint4* gsrc = B4 + (long)(nbase + bRow[l]) * 32 + (kc + 1) * 4 + bC4;
                cp_async16(bBn + (uint32_t)(bRow[l] * 80 + bC4 * 16), gsrc);
            }
            cp_commit();
            #pragma unroll
            for (int l = 0; l < 4; ++l)
                aPre[l] = A4[aRowG[l] * 64 + (kc + 1) * 8 + aC4];
        }

        #pragma unroll
        for (int s = 0; s < 2; ++s) {
            uint32_t ah[2][4];
            #pragma unroll
            for (int mi = 0; mi < 2; ++mi) {
                uint32_t o = aOff + (uint32_t)(mi * 16 * 80 + s * 32);
                ldsm_x4(ah[mi], aBase + o);
            }
            #pragma unroll
            for (int nj = 0; nj < 4; ++nj) {
                const int ni = nj * 2;
                uint32_t bo = bOffX4 + (uint32_t)(nj * 16 * 80 + s * 32);
                uint32_t bf[4];
                ldsm_x4(bf, bBase + bo);
                mma_f16(acc[0][ni],     ah[0], bf + 0);
                mma_f16(acc[0][ni + 1], ah[0], bf + 2);
                mma_f16(acc[1][ni],     ah[1], bf + 0);
                mma_f16(acc[1][ni + 1], ah[1], bf + 2);
            }
        }
    }

    if (EDGE) {
        const float scale = 0.17677669529663687f;  // 1/sqrt(32)
        #pragma unroll
        for (int mi = 0; mi < 2; ++mi) {
            #pragma unroll
            for (int rh = 0; rh < 2; ++rh) {
                int r  = wm * 32 + mi * 16 + qrow + rh * 8;
                int ge = row0 + r;
                const __half* Kr = g_Kh + (long)Ssrc[r] * DIMC + nbase + wn * 64;
                const __half* Qr = g_Qh + (long)Sdst[r] * DIMC + nbase + wn * 64;
                #pragma unroll
                for (int h = 0; h < 2; ++h) {
                    float p = 0.0f;
                    #pragma unroll
                    for (int j = 0; j < 4; ++j) {
                        int ni = h * 4 + j;
                        int c  = ni * 8 + quad * 2;
                        float2 kv = __half22float2(*(const __half2*)(Kr + c));
                        float2 qv = __half22float2(*(const __half2*)(Qr + c));
                        p += acc[mi][ni][rh * 2 + 0] * kv.x * qv.x;
                        p += acc[mi][ni][rh * 2 + 1] * kv.y * qv.y;
                    }
                    p += __shfl_xor_sync(0xffffffffu, p, 1);
                    p += __shfl_xor_sync(0xffffffffu, p, 2);
                    if (quad == 0 && ge < NE) {
                        float sv = fminf(5.0f, fmaxf(-5.0f, p * scale));
                        g_S[(long)ge * NH + (nbase >> 5) + wn * 2 + h] = expf(sv);
                    }
                }
            }
        }
    } else {
        int bx = blockIdx.x;
        __half* Cout = (bx < 2) ? g_Qh : (bx < 4) ? g_Kh : g_Vh;
        int colb = (bx & 1) * 128;
        #pragma unroll
        for (int mi = 0; mi < 2; ++mi) {
            #pragma unroll
            for (int ni = 0; ni < 8; ++ni) {
                int r = row0 + wm * 32 + mi * 16 + qrow;
                int c = colb + wn * 64 + ni * 8 + quad * 2;
                if (r < NN) {
                    __half2 v = __floats2half2_rn(acc[mi][ni][0], acc[mi][ni][1]);
                    *(__half2*)(Cout + (long)r * DIMC + c) = v;
                }
                if (r + 8 < NN) {
                    __half2 v = __floats2half2_rn(acc[mi][ni][2], acc[mi][ni][3]);
                    *(__half2*)(Cout + (long)(r + 8) * DIMC + c) = v;
                }
            }
        }
    }
}

// ---------------------------------------------------------------------------
// Gather + residual: one CTA per node; thread = column. No atomics.
// v2: edge metadata (src ids + all 8 head scores) staged into smem per
// 64-edge tile FIRST (index-independent), then the V loop issues 4
// independent V-row loads per step (MLP 4, no index->V dependence chain).
// ---------------------------------------------------------------------------
__global__ void gather_resid_kernel(const float* __restrict__ x,
                                    float* __restrict__ out) {
    __shared__ int ssrc[64];
    __shared__ float ss[64][NH];
    int n   = blockIdx.x;
    int tid = threadIdx.x;
    int h   = tid >> 5;
    int beg = g_off[n];
    int end = g_off[n + 1];

    float acc = 0.0f, zacc = 0.0f;
    for (int t = beg; t < end; t += 64) {
        int m = min(64, end - t);
        __syncthreads();                       // previous tile fully consumed
        if (tid < m) ssrc[tid] = g_psrc[t + tid];
        for (int p = tid; p < m * NH; p += 256) {
            int e = p >> 3, hh = p & 7;
            ss[e][hh] = g_S[(long)g_peid[t + e] * NH + hh];
        }
        __syncthreads();

        int i = 0;
        for (; i + 4 <= m; i += 4) {
            int s0 = ssrc[i], s1 = ssrc[i + 1], s2 = ssrc[i + 2], s3 = ssrc[i + 3];
            float v0 = __half2float(g_Vh[(long)s0 * DIMC + tid]);
            float v1 = __half2float(g_Vh[(long)s1 * DIMC + tid]);
            float v2 = __half2float(g_Vh[(long)s2 * DIMC + tid]);
            float v3 = __half2float(g_Vh[(long)s3 * DIMC + tid]);
            float w0 = ss[i][h], w1 = ss[i + 1][h];
            float w2 = ss[i + 2][h], w3 = ss[i + 3][h];
            acc += v0 * w0 + v1 * w1 + v2 * w2 + v3 * w3;
            zacc += (w0 + w1) + (w2 + w3);
        }
        for (; i < m; ++i) {
            float w = ss[i][h];
            acc += __half2float(g_Vh[(long)ssrc[i] * DIMC + tid]) * w;
            zacc += w;
        }
    }
    out[(long)n * DIMC + tid] = x[(long)n * DIMC + tid] + acc / (zacc + 1e-6f);
}

// ---------------------------------------------------------------------------
// BN column sums over out, then normalize.
// ---------------------------------------------------------------------------
__global__ void stats_kernel(const float* __restrict__ out) {
    int c = threadIdx.x;
    int r0 = blockIdx.x * 256;
    int rend = min(NN, r0 + 256);
    float s = 0.0f, s2 = 0.0f;
    for (int n = r0; n < rend; ++n) {
        float hv = out[(long)n * DIMC + c];
        s += hv;
        s2 += hv * hv;
    }
    atomicAdd(&g_cs[c], s);
    atomicAdd(&g_cs2[c], s2);
}

__global__ void bn_norm_kernel(float* __restrict__ out,
                               const float* __restrict__ gamma,
                               const float* __restrict__ beta) {
    long total = (long)NN * DIMC;
    long stride = (long)gridDim.x * blockDim.x;
    const float invN = 1.0f / (float)NN;
    for (long i = (long)blockIdx.x * blockDim.x + threadIdx.x; i < total; i += stride) {
        int c = (int)(i & (DIMC - 1));
        float mean = g_cs[c] * invN;
        float var = g_cs2[c] * invN - mean * mean;
        out[i] = (out[i] - mean) * rsqrtf(var + 1e-5f) * gamma[c] + beta[c];
    }
}

extern "C" void kernel_launch(void* const* d_in, const int* in_sizes, int n_in,
                              void* d_out, int out_size) {
    const float* x     = (const float*)d_in[0];
    const float* ea    = (const float*)d_in[1];
    const float* WQ    = (const float*)d_in[2];
    const float* WK    = (const float*)d_in[3];
    const float* WE    = (const float*)d_in[4];
    const float* WV    = (const float*)d_in[5];
    const float* gamma = (const float*)d_in[6];
    const float* beta  = (const float*)d_in[7];
    const long long* eidx = (const long long*)d_in[8];
    float* out = (float*)d_out;

    zero_kernel<<<NBLK, 256>>>();
    cvt_idx_kernel<<<512, 256>>>(eidx);
    scan1_kernel<<<NBLK, 256>>>();
    scan2_kernel<<<1, 512>>>();
    scan3_kernel<<<NBLK, 256>>>();
    build_kernel<<<(NE + 255) / 256, 256>>>();
    prep_w_kernel<<<1024, 256>>>(WQ, WK, WV, WE);

    // QKV: x = N-tile (6), y = row-tile (782) -> schedule-adjacent CTAs share A.
    mma_gemm_kernel<0><<<dim3(6, 782), 256, DYN_SMEM>>>(x);
    // Edge: x = N-tile (2), y = row-tile (3907).
    mma_gemm_kernel<1><<<dim3(2, 3907), 256, DYN_SMEM>>>(ea);

    gather_resid_kernel<<<NN, 256>>>(x, out);
    stats_kernel<<<NBLK, 256>>>(out);
    bn_norm_kernel<<<2048, 256>>>(out, gamma, beta);
}

// round 17
// speedup vs baseline: 1.2832x; 1.1795x over previous
#include <cuda_runtime.h>
#include <cuda_fp16.h>
#include <math.h>
#include <stdint.h>

#define NN 100000
#define NE 500000
#define DIMC 256
#define NH 8
#define NBLK 391   // ceil(NN/256)

// Dynamic smem layout (bytes):
//   A stage s (s=0,1): base + s*10240          (single fp16 copy of A chunk)
//   B stage s:         base + 20480 + s*10240  (single fp16 copy of W chunk)
#define A_STAGE_BYTES 10240
#define B_BASE        20480
#define B_STAGE_BYTES 10240
#define DYN_SMEM      40960

// ---------------------------------------------------------------------------
// Device-global scratch (no allocation allowed in kernel_launch)
// ---------------------------------------------------------------------------
__device__ __half g_Qh[NN * DIMC];
__device__ __half g_Kh[NN * DIMC];
__device__ __half g_Vh[NN * DIMC];
__device__ float g_S[NE * NH];
__device__ float g_cs[DIMC];
__device__ float g_cs2[DIMC];
__device__ int g_src[NE];
__device__ int g_dst[NE];
__device__ int g_cnt[NN];
__device__ int g_off[NN + 1];
__device__ int g_cur[NN];
__device__ int g_blkSum[512];
__device__ int g_psrc[NE];
__device__ int g_peid[NE];
__device__ __half g_W[768 * DIMC];    // [n][k], QKV concat, fp16 RN
__device__ __half g_WE[DIMC * DIMC];  // [n][k], fp16 RN

// ---------------------------------------------------------------------------
// Warp-MMA helpers (portable PTX: ldmatrix + mma.sync + cp.async, sm_80+)
// ---------------------------------------------------------------------------
__device__ __forceinline__ uint32_t smem_u32(const void* p) {
    uint32_t a;
    asm("{ .reg .u64 t; cvta.to.shared.u64 t, %1; cvt.u32.u64 %0, t; }"
        : "=r"(a) : "l"(p));
    return a;
}
__device__ __forceinline__ void ldsm_x4(uint32_t* r, uint32_t addr) {
    asm volatile("ldmatrix.sync.aligned.m8n8.x4.shared.b16 {%0,%1,%2,%3}, [%4];"
                 : "=r"(r[0]), "=r"(r[1]), "=r"(r[2]), "=r"(r[3]) : "r"(addr));
}
__device__ __forceinline__ void mma_f16(float* d, const uint32_t* a, const uint32_t* b) {
    asm volatile(
        "mma.sync.aligned.m16n8k16.row.col.f32.f16.f16.f32 "
        "{%0,%1,%2,%3}, {%4,%5,%6,%7}, {%8,%9}, {%0,%1,%2,%3};"
        : "+f"(d[0]), "+f"(d[1]), "+f"(d[2]), "+f"(d[3])
        : "r"(a[0]), "r"(a[1]), "r"(a[2]), "r"(a[3]), "r"(b[0]), "r"(b[1]));
}
__device__ __forceinline__ void cp_async16(uint32_t saddr, const void* gptr) {
    asm volatile("cp.async.cg.shared.global [%0], [%1], 16;"
                 :: "r"(saddr), "l"(gptr) : "memory");
}
__device__ __forceinline__ void cp_commit() {
    asm volatile("cp.async.commit_group;" ::: "memory");
}
__device__ __forceinline__ void cp_wait0() {
    asm volatile("cp.async.wait_group 0;" ::: "memory");
}

// ---------------------------------------------------------------------------
// Zero small accumulators (BN sums + histogram).
// ---------------------------------------------------------------------------
__global__ void zero_kernel() {
    int i = blockIdx.x * 256 + threadIdx.x;
    if (i < NN) g_cnt[i] = 0;
    if (i < DIMC) { g_cs[i] = 0.0f; g_cs2[i] = 0.0f; }
}

// ---------------------------------------------------------------------------
// edge_index -> int32 src/dst + dst histogram (int64 or int32 payload).
// ---------------------------------------------------------------------------
__global__ void cvt_idx_kernel(const long long* __restrict__ e64) {
    const int* e32 = (const int*)e64;
    bool is64 = true;
    #pragma unroll
    for (int i = 0; i < 64; ++i)
        if ((e64[i] >> 32) != 0) is64 = false;
    long stride = (long)gridDim.x * blockDim.x;
    for (long e = (long)blockIdx.x * blockDim.x + threadIdx.x; e < NE; e += stride) {
        int s, d;
        if (is64) { s = (int)e64[e]; d = (int)e64[NE + e]; }
        else      { s = e32[e];      d = e32[NE + e];      }
        g_src[e] = s;
        g_dst[e] = d;
        atomicAdd(&g_cnt[d], 1);
    }
}

// ---------------------------------------------------------------------------
// 3-kernel exclusive scan of g_cnt -> g_off / g_cur.
// ---------------------------------------------------------------------------
__global__ void scan1_kernel() {
    __shared__ int sh[256];
    int i = blockIdx.x * 256 + threadIdx.x;
    int v = (i < NN) ? g_cnt[i] : 0;
    sh[threadIdx.x] = v;
    __syncthreads();
    for (int d = 1; d < 256; d <<= 1) {
        int t = (threadIdx.x >= d) ? sh[threadIdx.x - d] : 0;
        __syncthreads();
        sh[threadIdx.x] += t;
        __syncthreads();
    }
    if (i < NN) g_off[i] = sh[threadIdx.x] - v;
    if (threadIdx.x == 255) g_blkSum[blockIdx.x] = sh[255];
}
__global__ void scan2_kernel() {
    __shared__ int sh[512];
    int v = (threadIdx.x < NBLK) ? g_blkSum[threadIdx.x] : 0;
    sh[threadIdx.x] = v;
    __syncthreads();
    for (int d = 1; d < 512; d <<= 1) {
        int t = (threadIdx.x >= d) ? sh[threadIdx.x - d] : 0;
        __syncthreads();
        sh[threadIdx.x] += t;
        __syncthreads();
    }
    if (threadIdx.x < NBLK) g_blkSum[threadIdx.x] = sh[threadIdx.x] - v;
}
__global__ void scan3_kernel() {
    int i = blockIdx.x * 256 + threadIdx.x;
    if (i < NN) {
        int o = g_off[i] + g_blkSum[blockIdx.x];
        g_off[i] = o;
        g_cur[i] = o;
    }
    if (i == 0) g_off[NN] = NE;
}

// ---------------------------------------------------------------------------
// Build dst-sorted edge list (CSR payload).
// ---------------------------------------------------------------------------
__global__ void build_kernel() {
    int e = blockIdx.x * 256 + threadIdx.x;
    if (e < NE) {
        int d = g_dst[e];
        int pos = atomicAdd(&g_cur[d], 1);
        g_psrc[pos] = g_src[e];
        g_peid[pos] = e;
    }
}

// ---------------------------------------------------------------------------
// Weights transposed into B-operand layout [n][k], fp16 round-to-nearest.
// ---------------------------------------------------------------------------
__global__ void prep_w_kernel(const float* __restrict__ WQ, const float* __restrict__ WK,
                              const float* __restrict__ WV, const float* __restrict__ WE) {
    int i = blockIdx.x * 256 + threadIdx.x;
    if (i < 768 * DIMC) {
        int n = i >> 8;
        int k = i & 255;
        int m = n >> 8, nn = n & 255;
        const float* W = (m == 0) ? WQ : (m == 1) ? WK : WV;
        g_W[i] = __float2half_rn(W[k * DIMC + nn]);
    } else {
        int j = i - 768 * DIMC;
        int n = j >> 8, k = j & 255;
        g_WE[j] = __float2half_rn(WE[k * DIMC + n]);
    }
}

// ---------------------------------------------------------------------------
// Convert & store one A chunk (4 float4 per thread) to fp16 smem stage.
// ---------------------------------------------------------------------------
__device__ __forceinline__ void stsA(char* stage, const float4* v4,
                                     const int* aRow, int aC4) {
    __half* sA = (__half*)stage;
    #pragma unroll
    for (int l = 0; l < 4; ++l) {
        float4 v = v4[l];
        __half2 h01 = __floats2half2_rn(v.x, v.y);
        __half2 h23 = __floats2half2_rn(v.z, v.w);
        int row = aRow[l];
        *(uint2*)(sA + row * 40 + aC4 * 4) =
            make_uint2(*(uint32_t*)&h01, *(uint32_t*)&h23);
    }
}

// ---------------------------------------------------------------------------
// Warp-MMA fp16 GEMM (1-pass), 128x128 block tile, K=256 in 8 chunks of 32.
// (round-14 best, byte-identical)
// EDGE=0: writes Q/K/V as fp16.  EDGE=1: per-edge head-score epilogue -> g_S.
// ---------------------------------------------------------------------------
template<int EDGE>
__global__ void __launch_bounds__(256, 2) mma_gemm_kernel(const float* __restrict__ Asrc) {
    extern __shared__ __align__(16) char dsm[];
    __shared__ int Ssrc[128], Sdst[128];

    const int tid  = threadIdx.x;
    const int wid  = tid >> 5;
    const int lane = tid & 31;
    const int wm   = wid & 3;
    const int wn   = wid >> 2;
    const int quad = lane & 3;
    const int qrow = lane >> 2;

    const int row0  = blockIdx.y * 128;
    const int nbase = blockIdx.x * 128;
    const int Mtot  = EDGE ? NE : NN;

    if (EDGE && tid < 128) {
        int ge = row0 + tid;
        if (ge > NE - 1) ge = NE - 1;
        Ssrc[tid] = g_src[ge];
        Sdst[tid] = g_dst[ge];
    }

    const float4* A4 = (const float4*)Asrc;
    const uint4* B4 = EDGE ? (const uint4*)g_WE : (const uint4*)g_W;

    float acc[2][8][4] = {};

    const uint32_t base = smem_u32(dsm);
    const uint32_t aOff = (uint32_t)((wm * 32 + (lane & 15)) * 80 + (lane >> 4) * 16);
    const uint32_t bOffX4 = (uint32_t)((wn * 64 + (lane & 7) + (lane >> 4) * 8) * 80 +
                                       ((lane >> 3) & 1) * 16);

    const int aRow[4] = { (tid + 0) >> 3, (tid + 256) >> 3, (tid + 512) >> 3, (tid + 768) >> 3 };
    const int aC4 = tid & 7;
    long aRowG[4];
    #pragma unroll
    for (int l = 0; l < 4; ++l) aRowG[l] = min(row0 + aRow[l], Mtot - 1);
    const int bRow[2] = { (tid + 0) >> 2, (tid + 256) >> 2 };
    const int bC4 = tid & 3;

    float4 aPre[4];
    #pragma unroll
    for (int l = 0; l < 4; ++l) aPre[l] = A4[aRowG[l] * 64 + 0 + aC4];
    {
        uint32_t bB = base + B_BASE;
        #pragma unroll
        for (int l = 0; l < 2; ++l) {
            const uint4* gsrc = B4 + (long)(nbase + bRow[l]) * 32 + 0 + bC4;
            cp_async16(bB + (uint32_t)(bRow[l] * 80 + bC4 * 16), gsrc);
        }
        cp_commit();
    }

    for (int kc = 0; kc < 8; ++kc) {
        const int st = kc & 1;
        const uint32_t aBase = base + st * A_STAGE_BYTES;
        const uint32_t bBase = base + B_BASE + st * B_STAGE_BYTES;

        stsA(dsm + st * A_STAGE_BYTES, aPre, aRow, aC4);

        cp_wait0();
        __syncthreads();

        if (kc < 7) {
            uint32_t bBn = base + B_BASE + (st ^ 1) * B_STAGE_BYTES;
            #pragma unroll
            for (int l = 0; l < 2; ++l) {
                const uint4* gsrc = B4 + (long)(nbase + bRow[l]) * 32 + (kc + 1) * 4 + bC4;
                cp_async16(bBn + (uint32_t)(bRow[l] * 80 + bC4 * 16), gsrc);
            }
            cp_commit();
            #pragma unroll
            for (int l = 0; l < 4; ++l)
                aPre[l] = A4[aRowG[l] * 64 + (kc + 1) * 8 + aC4];
        }

        #pragma unroll
        for (int s = 0; s < 2; ++s) {
            uint32_t ah[2][4];
            #pragma unroll
            for (int mi = 0; mi < 2; ++mi) {
                uint32_t o = aOff + (uint32_t)(mi * 16 * 80 + s * 32);
                ldsm_x4(ah[mi], aBase + o);
            }
            #pragma unroll
            for (int nj = 0; nj < 4; ++nj) {
                const int ni = nj * 2;
                uint32_t bo = bOffX4 + (uint32_t)(nj * 16 * 80 + s * 32);
                uint32_t bf[4];
                ldsm_x4(bf, bBase + bo);
                mma_f16(acc[0][ni],     ah[0], bf + 0);
                mma_f16(acc[0][ni + 1], ah[0], bf + 2);
                mma_f16(acc[1][ni],     ah[1], bf + 0);
                mma_f16(acc[1][ni + 1], ah[1], bf + 2);
            }
        }
    }

    if (EDGE) {
        const float scale = 0.17677669529663687f;  // 1/sqrt(32)
        #pragma unroll
        for (int mi = 0; mi < 2; ++mi) {
            #pragma unroll
            for (int rh = 0; rh < 2; ++rh) {
                int r  = wm * 32 + mi * 16 + qrow + rh * 8;
                int ge = row0 + r;
                const __half* Kr = g_Kh + (long)Ssrc[r] * DIMC + nbase + wn * 64;
                const __half* Qr = g_Qh + (long)Sdst[r] * DIMC + nbase + wn * 64;
                #pragma unroll
                for (int h = 0; h < 2; ++h) {
                    float p = 0.0f;
                    #pragma unroll
                    for (int j = 0; j < 4; ++j) {
                        int ni = h * 4 + j;
                        int c  = ni * 8 + quad * 2;
                        float2 kv = __half22float2(*(const __half2*)(Kr + c));
                        float2 qv = __half22float2(*(const __half2*)(Qr + c));
                        p += acc[mi][ni][rh * 2 + 0] * kv.x * qv.x;
                        p += acc[mi][ni][rh * 2 + 1] * kv.y * qv.y;
                    }
                    p += __shfl_xor_sync(0xffffffffu, p, 1);
                    p += __shfl_xor_sync(0xffffffffu, p, 2);
                    if (quad == 0 && ge < NE) {
                        float sv = fminf(5.0f, fmaxf(-5.0f, p * scale));
                        g_S[(long)ge * NH + (nbase >> 5) + wn * 2 + h] = expf(sv);
                    }
                }
            }
        }
    } else {
        int bx = blockIdx.x;
        __half* Cout = (bx < 2) ? g_Qh : (bx < 4) ? g_Kh : g_Vh;
        int colb = (bx & 1) * 128;
        #pragma unroll
        for (int mi = 0; mi < 2; ++mi) {
            #pragma unroll
            for (int ni = 0; ni < 8; ++ni) {
                int r = row0 + wm * 32 + mi * 16 + qrow;
                int c = colb + wn * 64 + ni * 8 + quad * 2;
                if (r < NN) {
                    __half2 v = __floats2half2_rn(acc[mi][ni][0], acc[mi][ni][1]);
                    *(__half2*)(Cout + (long)r * DIMC + c) = v;
                }
                if (r + 8 < NN) {
                    __half2 v = __floats2half2_rn(acc[mi][ni][2], acc[mi][ni][3]);
                    *(__half2*)(Cout + (long)(r + 8) * DIMC + c) = v;
                }
            }
        }
    }
}

// ---------------------------------------------------------------------------
// Gather + residual: one CTA (128 threads) per node; thread = column pair.
// Sync-free (avg degree ~5). Unroll 4 with batched independent index loads
// -> 4 S loads and 4 half2 V loads in flight (MLP 4-8).
// ---------------------------------------------------------------------------
__global__ void gather_resid_kernel(const float* __restrict__ x,
                                    float* __restrict__ out) {
    int n   = blockIdx.x;
    int tid = threadIdx.x;       // 0..127
    int c   = tid * 2;
    int h   = c >> 5;
    int beg = g_off[n];
    int end = g_off[n + 1];

    float ax = 0.0f, ay = 0.0f, zacc = 0.0f;
    int e = beg;
    for (; e + 4 <= end; e += 4) {
        int s0 = g_psrc[e], s1 = g_psrc[e + 1], s2 = g_psrc[e + 2], s3 = g_psrc[e + 3];
        int i0 = g_peid[e], i1 = g_peid[e + 1], i2 = g_peid[e + 2], i3 = g_peid[e + 3];
        float w0 = g_S[(long)i0 * NH + h];
        float w1 = g_S[(long)i1 * NH + h];
        float w2 = g_S[(long)i2 * NH + h];
        float w3 = g_S[(long)i3 * NH + h];
        float2 v0 = __half22float2(*(const __half2*)(g_Vh + (long)s0 * DIMC + c));
        float2 v1 = __half22float2(*(const __half2*)(g_Vh + (long)s1 * DIMC + c));
        float2 v2 = __half22float2(*(const __half2*)(g_Vh + (long)s2 * DIMC + c));
        float2 v3 = __half22float2(*(const __half2*)(g_Vh + (long)s3 * DIMC + c));
        ax += v0.x * w0 + v1.x * w1 + v2.x * w2 + v3.x * w3;
        ay += v0.y * w0 + v1.y * w1 + v2.y * w2 + v3.y * w3;
        zacc += (w0 + w1) + (w2 + w3);
    }
    for (; e < end; ++e) {
        int s0 = g_psrc[e];
        int i0 = g_peid[e];
        float w0 = g_S[(long)i0 * NH + h];
        float2 v0 = __half22float2(*(const __half2*)(g_Vh + (long)s0 * DIMC + c));
        ax += v0.x * w0;
        ay += v0.y * w0;
        zacc += w0;
    }
    float inv = 1.0f / (zacc + 1e-6f);
    float2 xr = *(const float2*)(x + (long)n * DIMC + c);
    *(float2*)(out + (long)n * DIMC + c) = make_float2(xr.x + ax * inv, xr.y + ay * inv);
}

// ---------------------------------------------------------------------------
// BN column sums over out, then normalize.
// ---------------------------------------------------------------------------
__global__ void stats_kernel(const float* __restrict__ out) {
    int c = threadIdx.x;
    int r0 = blockIdx.x * 256;
    int rend = min(NN, r0 + 256);
    float s = 0.0f, s2 = 0.0f;
    for (int n = r0; n < rend; ++n) {
        float hv = out[(long)n * DIMC + c];
        s += hv;
        s2 += hv * hv;
    }
    atomicAdd(&g_cs[c], s);
    atomicAdd(&g_cs2[c], s2);
}

__global__ void bn_norm_kernel(float* __restrict__ out,
                               const float* __restrict__ gamma,
                               const float* __restrict__ beta) {
    long total = (long)NN * DIMC;
    long stride = (long)gridDim.x * blockDim.x;
    const float invN = 1.0f / (float)NN;
    for (long i = (long)blockIdx.x * blockDim.x + threadIdx.x; i < total; i += stride) {
        int c = (int)(i & (DIMC - 1));
        float mean = g_cs[c] * invN;
        float var = g_cs2[c] * invN - mean * mean;
        out[i] = (out[i] - mean) * rsqrtf(var + 1e-5f) * gamma[c] + beta[c];
    }
}

extern "C" void kernel_launch(void* const* d_in, const int* in_sizes, int n_in,
                              void* d_out, int out_size) {
    const float* x     = (const float*)d_in[0];
    const float* ea    = (const float*)d_in[1];
    const float* WQ    = (const float*)d_in[2];
    const float* WK    = (const float*)d_in[3];
    const float* WE    = (const float*)d_in[4];
    const float* WV    = (const float*)d_in[5];
    const float* gamma = (const float*)d_in[6];
    const float* beta  = (const float*)d_in[7];
    const long long* eidx = (const long long*)d_in[8];
    float* out = (float*)d_out;

    zero_kernel<<<NBLK, 256>>>();
    cvt_idx_kernel<<<512, 256>>>(eidx);
    scan1_kernel<<<NBLK, 256>>>();
    scan2_kernel<<<1, 512>>>();
    scan3_kernel<<<NBLK, 256>>>();
    build_kernel<<<(NE + 255) / 256, 256>>>();
    prep_w_kernel<<<1024, 256>>>(WQ, WK, WV, WE);

    // QKV: x = N-tile (6), y = row-tile (782) -> schedule-adjacent CTAs share A.
    mma_gemm_kernel<0><<<dim3(6, 782), 256, DYN_SMEM>>>(x);
    // Edge: x = N-tile (2), y = row-tile (3907).
    mma_gemm_kernel<1><<<dim3(2, 3907), 256, DYN_SMEM>>>(ea);

    gather_resid_kernel<<<NN, 128>>>(x, out);
    stats_kernel<<<NBLK, 256>>>(out);
    bn_norm_kernel<<<2048, 256>>>(out, gamma, beta);
}